// round 2
// baseline (speedup 1.0000x reference)
#include <cuda_runtime.h>

// Problem constants
#define BSZ     2
#define HEADS   8
#define DIM     32
#define SEQ     4096           // 64*64
#define QTILE   256            // queries per CTA (2 per thread)
#define KTILE   128            // keys per tile (two p-rows)
#define NTHREADS 128

typedef unsigned long long u64;

__device__ __forceinline__ u64 pk2(float lo, float hi) {
    u64 r; asm("mov.b64 %0,{%1,%2};" : "=l"(r) : "f"(lo), "f"(hi)); return r;
}
__device__ __forceinline__ void upk2(float& lo, float& hi, u64 p) {
    asm("mov.b64 {%0,%1},%2;" : "=f"(lo), "=f"(hi) : "l"(p));
}
__device__ __forceinline__ u64 ffma2(u64 a, u64 b, u64 c) {
    u64 d; asm("fma.rn.f32x2 %0,%1,%2,%3;" : "=l"(d) : "l"(a), "l"(b), "l"(c)); return d;
}
__device__ __forceinline__ u64 fmul2(u64 a, u64 b) {
    u64 d; asm("mul.rn.f32x2 %0,%1,%2;" : "=l"(d) : "l"(a), "l"(b)); return d;
}

// Dynamic smem (float4 units):
//   sK4 : KTILE*8 = 1024   (augmented K' tile)
//   sV4 : 1024
//   sEH4: 64*8 = 512
//   sEW4: 512
// total 3072 float4 = 49152 B -> 2 CTAs/SM
#define SMEM_BYTES (3072 * 16)

__global__ void __launch_bounds__(NTHREADS, 2)
abspos_attn_kernel(const float* __restrict__ q,
                   const float* __restrict__ k,
                   const float* __restrict__ v,
                   const float* __restrict__ eh,
                   const float* __restrict__ ew,
                   float* __restrict__ out)
{
    extern __shared__ float4 smem4[];
    float4* sK4  = smem4;
    float4* sV4  = sK4 + KTILE * 8;
    float4* sEH4 = sV4 + KTILE * 8;
    float4* sEW4 = sEH4 + 64 * 8;
    const ulonglong2* sK2 = reinterpret_cast<const ulonglong2*>(sK4);
    const ulonglong2* sV2 = reinterpret_cast<const ulonglong2*>(sV4);

    const int tid = threadIdx.x;
    const int bn  = blockIdx.y;                    // b*HEADS + n
    const int q0  = blockIdx.x * QTILE + tid;      // query A
    const int q1  = q0 + NTHREADS;                 // query B

    // ---- preload emb tables into smem (shared by tile augmentation) ----
    {
        const float4* ehg = reinterpret_cast<const float4*>(eh);
        const float4* ewg = reinterpret_cast<const float4*>(ew);
        #pragma unroll
        for (int i = 0; i < 4; i++) {
            sEH4[tid + i * NTHREADS] = ehg[tid + i * NTHREADS];
            sEW4[tid + i * NTHREADS] = ewg[tid + i * NTHREADS];
        }
    }

    // ---- load both queries, pre-scaled, packed as f32x2 over D ----
    const float scale = 0.17677669529663687f;      // 32^-0.5
    u64 qA2[DIM / 2], qB2[DIM / 2];
    {
        const float4* qgA = reinterpret_cast<const float4*>(
            q + ((size_t)bn * SEQ + q0) * DIM);
        const float4* qgB = reinterpret_cast<const float4*>(
            q + ((size_t)bn * SEQ + q1) * DIM);
        #pragma unroll
        for (int i = 0; i < DIM / 4; i++) {
            float4 a = qgA[i], b = qgB[i];
            qA2[2 * i]     = pk2(a.x * scale, a.y * scale);
            qA2[2 * i + 1] = pk2(a.z * scale, a.w * scale);
            qB2[2 * i]     = pk2(b.x * scale, b.y * scale);
            qB2[2 * i + 1] = pk2(b.z * scale, b.w * scale);
        }
    }

    // ---- online softmax state (accumulators packed f32x2 over D) ----
    float mA = -1e30f, lA = 0.f, mB = -1e30f, lB = 0.f;
    u64 accA[DIM / 2], accB[DIM / 2];
    #pragma unroll
    for (int i = 0; i < DIM / 2; i++) { accA[i] = 0ull; accB[i] = 0ull; }

    const float4* kbase = reinterpret_cast<const float4*>(k + (size_t)bn * SEQ * DIM);
    const float4* vbase = reinterpret_cast<const float4*>(v + (size_t)bn * SEQ * DIM);

    __syncthreads();  // emb tables ready

    for (int t = 0; t < SEQ / KTILE; t++) {
        if (t) __syncthreads();  // retire reads of previous tile
        // ---- load tile; fold bias into K: K' = k + eh[p] + ew[w] ----
        {
            const float4* kg = kbase + t * KTILE * 8;
            const float4* vg = vbase + t * KTILE * 8;
            #pragma unroll
            for (int it = 0; it < KTILE * 8 / NTHREADS; it++) {
                int i  = tid + it * NTHREADS;
                int d4 = i & 7;
                int j  = i >> 3;                       // key within tile 0..127
                float4 kv = kg[i];
                float4 hv = sEH4[((t << 1) + (j >> 6)) * 8 + d4];
                float4 wv = sEW4[(j & 63) * 8 + d4];
                kv.x += hv.x + wv.x; kv.y += hv.y + wv.y;
                kv.z += hv.z + wv.z; kv.w += hv.w + wv.w;
                sK4[i] = kv;
                sV4[i] = vg[i];
            }
        }
        __syncthreads();

        #pragma unroll 1
        for (int j0 = 0; j0 < KTILE; j0 += 8) {
            // ---- scores for 8 keys x 2 queries (packed over D) ----
            u64 sA2[8], sB2[8];
            #pragma unroll
            for (int jj = 0; jj < 8; jj++) { sA2[jj] = 0ull; sB2[jj] = 0ull; }
            #pragma unroll
            for (int d4 = 0; d4 < 8; d4++) {
                const u64 qa0 = qA2[2 * d4], qa1 = qA2[2 * d4 + 1];
                const u64 qb0 = qB2[2 * d4], qb1 = qB2[2 * d4 + 1];
                #pragma unroll
                for (int jj = 0; jj < 8; jj++) {
                    ulonglong2 kk = sK2[(j0 + jj) * 8 + d4];
                    sA2[jj] = ffma2(qa0, kk.x, sA2[jj]);
                    sA2[jj] = ffma2(qa1, kk.y, sA2[jj]);
                    sB2[jj] = ffma2(qb0, kk.x, sB2[jj]);
                    sB2[jj] = ffma2(qb1, kk.y, sB2[jj]);
                }
            }
            // ---- horizontal sum + online softmax, both queries ----
            float sA[8], sB[8];
            #pragma unroll
            for (int jj = 0; jj < 8; jj++) {
                float lo, hi;
                upk2(lo, hi, sA2[jj]); sA[jj] = lo + hi;
                upk2(lo, hi, sB2[jj]); sB[jj] = lo + hi;
            }
            float mtA = mA, mtB = mB;
            #pragma unroll
            for (int jj = 0; jj < 8; jj++) {
                mtA = fmaxf(mtA, sA[jj]);
                mtB = fmaxf(mtB, sB[jj]);
            }
            const float fA = __expf(mA - mtA);
            const float fB = __expf(mB - mtB);
            mA = mtA; mB = mtB;
            float pA[8], pB[8], lsA = 0.f, lsB = 0.f;
            #pragma unroll
            for (int jj = 0; jj < 8; jj++) {
                pA[jj] = __expf(sA[jj] - mtA); lsA += pA[jj];
                pB[jj] = __expf(sB[jj] - mtB); lsB += pB[jj];
            }
            lA = fmaf(lA, fA, lsA);
            lB = fmaf(lB, fB, lsB);
            // ---- rescale accumulators ----
            const u64 fA2 = pk2(fA, fA), fB2 = pk2(fB, fB);
            #pragma unroll
            for (int i = 0; i < DIM / 2; i++) {
                accA[i] = fmul2(accA[i], fA2);
                accB[i] = fmul2(accB[i], fB2);
            }
            // ---- PV accumulate (jj outer so acc-chains are spaced) ----
            u64 pA2[8], pB2[8];
            #pragma unroll
            for (int jj = 0; jj < 8; jj++) {
                pA2[jj] = pk2(pA[jj], pA[jj]);
                pB2[jj] = pk2(pB[jj], pB[jj]);
            }
            #pragma unroll
            for (int jj = 0; jj < 8; jj++) {
                const u64 wa = pA2[jj], wb = pB2[jj];
                #pragma unroll
                for (int d4 = 0; d4 < 8; d4++) {
                    ulonglong2 vv = sV2[(j0 + jj) * 8 + d4];
                    accA[2 * d4]     = ffma2(wa, vv.x, accA[2 * d4]);
                    accA[2 * d4 + 1] = ffma2(wa, vv.y, accA[2 * d4 + 1]);
                    accB[2 * d4]     = ffma2(wb, vv.x, accB[2 * d4]);
                    accB[2 * d4 + 1] = ffma2(wb, vv.y, accB[2 * d4 + 1]);
                }
            }
        }
    }

    // ---- write out: out[b, x, y, n*DIM + d] ----
    const int b = bn / HEADS, n = bn % HEADS;
    const float invA = 1.0f / lA;
    const float invB = 1.0f / lB;
    float4* ogA = reinterpret_cast<float4*>(
        out + ((size_t)b * SEQ + q0) * (HEADS * DIM) + n * DIM);
    float4* ogB = reinterpret_cast<float4*>(
        out + ((size_t)b * SEQ + q1) * (HEADS * DIM) + n * DIM);
    #pragma unroll
    for (int d4 = 0; d4 < DIM / 4; d4++) {
        float x0, x1, x2, x3, y0, y1, y2, y3;
        upk2(x0, x1, accA[2 * d4]); upk2(x2, x3, accA[2 * d4 + 1]);
        upk2(y0, y1, accB[2 * d4]); upk2(y2, y3, accB[2 * d4 + 1]);
        ogA[d4] = make_float4(x0 * invA, x1 * invA, x2 * invA, x3 * invA);
        ogB[d4] = make_float4(y0 * invB, y1 * invB, y2 * invB, y3 * invB);
    }
}

extern "C" void kernel_launch(void* const* d_in, const int* in_sizes, int n_in,
                              void* d_out, int out_size)
{
    const float* q  = (const float*)d_in[0];
    const float* k  = (const float*)d_in[1];
    const float* v  = (const float*)d_in[2];
    const float* eh = (const float*)d_in[3];
    const float* ew = (const float*)d_in[4];
    float* out = (float*)d_out;

    static bool attr_set = false;
    if (!attr_set) {
        cudaFuncSetAttribute(abspos_attn_kernel,
                             cudaFuncAttributeMaxDynamicSharedMemorySize,
                             SMEM_BYTES);
        attr_set = true;
    }

    dim3 grid(SEQ / QTILE, BSZ * HEADS);   // 16 x 16 = 256 CTAs
    abspos_attn_kernel<<<grid, NTHREADS, SMEM_BYTES>>>(q, k, v, eh, ew, out);
}

// round 5
// speedup vs baseline: 3.3995x; 3.3995x over previous
#include <cuda_runtime.h>
#include <cuda_bf16.h>
#include <cstdint>

// ---------------- problem constants ----------------
#define BSZ     2
#define HEADS   8
#define DIM     32
#define SEQ     4096
#define QT      64             // queries per CTA (16 per warp)
#define KT      64             // keys per tile
#define NTILES  (SEQ / KT)     // 64
#define THREADS 128

// pack two f32 -> bf16x2 (lo in low half)
__device__ __forceinline__ uint32_t cvt2(float lo, float hi) {
    uint32_t r;
    asm("cvt.rn.bf16x2.f32 %0, %1, %2;" : "=r"(r) : "f"(hi), "f"(lo));
    return r;
}
// error-compensated split: (x0,x1) -> hi bf16x2 + lo bf16x2
__device__ __forceinline__ void split2(float x0, float x1, uint32_t& h, uint32_t& l) {
    h = cvt2(x0, x1);
    float h0 = __uint_as_float(h << 16);
    float h1 = __uint_as_float(h & 0xFFFF0000u);
    l = cvt2(x0 - h0, x1 - h1);
}

__device__ __forceinline__ void mma16816(float* c, const uint32_t* a, const uint32_t* b) {
    asm volatile(
        "mma.sync.aligned.m16n8k16.row.col.f32.bf16.bf16.f32 "
        "{%0,%1,%2,%3},{%4,%5,%6,%7},{%8,%9},{%0,%1,%2,%3};"
        : "+f"(c[0]), "+f"(c[1]), "+f"(c[2]), "+f"(c[3])
        : "r"(a[0]), "r"(a[1]), "r"(a[2]), "r"(a[3]), "r"(b[0]), "r"(b[1]));
}

// 16B-chunk XOR swizzle inside a 128B row
__device__ __forceinline__ int swz(int row, int chunk) {
    return row * 128 + ((chunk ^ (row & 7)) << 4);
}

__global__ void __launch_bounds__(THREADS, 4)
abspos_attn_mma(const float* __restrict__ q,
                const float* __restrict__ k,
                const float* __restrict__ v,
                const float* __restrict__ eh,
                const float* __restrict__ ew,
                float* __restrict__ out)
{
    // K' rows: 64 keys x 128B = [Kh 32d bf16 | Kl 32d bf16], chunk-swizzled
    // V^T rows: 32 d x 128B = 64 keys bf16, hi and lo buffers
    __shared__ __align__(16) uint8_t sK [64 * 128];
    __shared__ __align__(16) uint8_t sVh[32 * 128];
    __shared__ __align__(16) uint8_t sVl[32 * 128];

    const int tid  = threadIdx.x;
    const int warp = tid >> 5;
    const int lane = tid & 31;
    const int g    = lane >> 2;      // group id 0..7
    const int tg   = lane & 3;       // thread-in-group

    const int bn    = blockIdx.y;            // b*HEADS + n
    const int qbase = blockIdx.x * QT;

    const float4* kb4 = reinterpret_cast<const float4*>(k + (size_t)bn * SEQ * DIM);
    const float*  vb  = v + (size_t)bn * SEQ * DIM;
    const float4* eh4 = reinterpret_cast<const float4*>(eh);
    const float4* ew4 = reinterpret_cast<const float4*>(ew);

    // ---- load Q fragments (row g and g+8 of this warp's 16 queries) ----
    // aq[ks][0..3]: a0(row g, d=16ks+2tg), a1(row g+8, same), a2(row g, +8), a3(row g+8, +8)
    uint32_t aqh[2][4], aql[2][4];
    {
        const float scale = 0.17677669529663687f;   // 32^-0.5
        const int qrow0 = qbase + warp * 16 + g;
        const float* qp0 = q + ((size_t)bn * SEQ + qrow0) * DIM;
        const float* qp1 = qp0 + 8 * DIM;
        #pragma unroll
        for (int ks = 0; ks < 2; ks++) {
            #pragma unroll
            for (int half = 0; half < 2; half++) {
                int d = 16 * ks + 8 * half + 2 * tg;
                float2 r0 = *reinterpret_cast<const float2*>(qp0 + d);
                float2 r1 = *reinterpret_cast<const float2*>(qp1 + d);
                split2(r0.x * scale, r0.y * scale, aqh[ks][2 * half],     aql[ks][2 * half]);
                split2(r1.x * scale, r1.y * scale, aqh[ks][2 * half + 1], aql[ks][2 * half + 1]);
            }
        }
    }

    // ---- persistent state ----
    float oc[4][4];                 // O fragments: 4 n-tiles of 8 d
    #pragma unroll
    for (int i = 0; i < 4; i++)
        #pragma unroll
        for (int e = 0; e < 4; e++) oc[i][e] = 0.f;
    float lsum0 = 0.f, lsum1 = 0.f;   // row g, row g+8 partial softmax sums

    // staging thread roles
    const int jk = tid >> 1, hk = tid & 1;     // K': key jk, d-half hk
    const int dv = tid & 31, kg = tid >> 5;    // V : d, key-group of 16

    for (int t = 0; t < NTILES; t++) {
        // ---- stage gmem -> regs (overlap with other CTAs' compute) ----
        float4 kf[4];
        {
            const float4* kp4 = kb4 + (size_t)t * 512 + jk * 8 + hk * 4;
            #pragma unroll
            for (int i = 0; i < 4; i++) kf[i] = kp4[i];
        }
        float vf[16];
        {
            const float* vp = vb + ((size_t)t * 64 + kg * 16) * DIM + dv;
            #pragma unroll
            for (int i = 0; i < 16; i++) vf[i] = vp[i * DIM];
        }

        __syncthreads();   // previous tile's smem reads complete

        // ---- write K' = K + eh[t] + ew[j], split hi/lo ----
        {
            uint32_t hi[8], lo[8];
            #pragma unroll
            for (int i = 0; i < 4; i++) {
                float4 ev = eh4[t * 8 + hk * 4 + i];
                float4 wv = ew4[jk * 8 + hk * 4 + i];
                float x0 = kf[i].x + ev.x + wv.x;
                float x1 = kf[i].y + ev.y + wv.y;
                float x2 = kf[i].z + ev.z + wv.z;
                float x3 = kf[i].w + ev.w + wv.w;
                split2(x0, x1, hi[2 * i],     lo[2 * i]);
                split2(x2, x3, hi[2 * i + 1], lo[2 * i + 1]);
            }
            *reinterpret_cast<uint4*>(sK + swz(jk, 2 * hk))     = make_uint4(hi[0], hi[1], hi[2], hi[3]);
            *reinterpret_cast<uint4*>(sK + swz(jk, 2 * hk + 1)) = make_uint4(hi[4], hi[5], hi[6], hi[7]);
            *reinterpret_cast<uint4*>(sK + swz(jk, 2 * hk + 4)) = make_uint4(lo[0], lo[1], lo[2], lo[3]);
            *reinterpret_cast<uint4*>(sK + swz(jk, 2 * hk + 5)) = make_uint4(lo[4], lo[5], lo[6], lo[7]);
        }
        // ---- write V^T (d-major), split hi/lo ----
        {
            uint32_t hv[8], lv[8];
            #pragma unroll
            for (int i = 0; i < 8; i++)
                split2(vf[2 * i], vf[2 * i + 1], hv[i], lv[i]);
            *reinterpret_cast<uint4*>(sVh + swz(dv, 2 * kg))     = make_uint4(hv[0], hv[1], hv[2], hv[3]);
            *reinterpret_cast<uint4*>(sVh + swz(dv, 2 * kg + 1)) = make_uint4(hv[4], hv[5], hv[6], hv[7]);
            *reinterpret_cast<uint4*>(sVl + swz(dv, 2 * kg))     = make_uint4(lv[0], lv[1], lv[2], lv[3]);
            *reinterpret_cast<uint4*>(sVl + swz(dv, 2 * kg + 1)) = make_uint4(lv[4], lv[5], lv[6], lv[7]);
        }
        __syncthreads();

        // ---- S = Q'.K'^T  (8 n-tiles of 8 keys), 3-term split ----
        float c[8][4];
        #pragma unroll
        for (int nt = 0; nt < 8; nt++) {
            #pragma unroll
            for (int e = 0; e < 4; e++) c[nt][e] = 0.f;
            const uint8_t* kr = sK + (nt * 8 + g) * 128;
            const int boff = 4 * tg;
            #pragma unroll
            for (int ks = 0; ks < 2; ks++) {
                uint32_t bh[2], bl[2];
                bh[0] = *reinterpret_cast<const uint32_t*>(kr + (((2 * ks)     ^ g) << 4) + boff);
                bh[1] = *reinterpret_cast<const uint32_t*>(kr + (((2 * ks + 1) ^ g) << 4) + boff);
                bl[0] = *reinterpret_cast<const uint32_t*>(kr + (((2 * ks + 4) ^ g) << 4) + boff);
                bl[1] = *reinterpret_cast<const uint32_t*>(kr + (((2 * ks + 5) ^ g) << 4) + boff);
                mma16816(c[nt], aqh[ks], bh);   // Qh.Kh
                mma16816(c[nt], aqh[ks], bl);   // Qh.Kl
                mma16816(c[nt], aql[ks], bh);   // Ql.Kh
            }
        }

        // ---- softmax (no max subtraction; logits bounded) ----
        #pragma unroll
        for (int nt = 0; nt < 8; nt++) {
            c[nt][0] = __expf(c[nt][0]);
            c[nt][1] = __expf(c[nt][1]);
            c[nt][2] = __expf(c[nt][2]);
            c[nt][3] = __expf(c[nt][3]);
            lsum0 += c[nt][0] + c[nt][1];
            lsum1 += c[nt][2] + c[nt][3];
        }

        // ---- repack P (C-frag -> A-frag), split hi/lo ----
        uint32_t aPh[4][4], aPl[4][4];
        #pragma unroll
        for (int kp = 0; kp < 4; kp++) {
            split2(c[2 * kp][0],     c[2 * kp][1],     aPh[kp][0], aPl[kp][0]);
            split2(c[2 * kp][2],     c[2 * kp][3],     aPh[kp][1], aPl[kp][1]);
            split2(c[2 * kp + 1][0], c[2 * kp + 1][1], aPh[kp][2], aPl[kp][2]);
            split2(c[2 * kp + 1][2], c[2 * kp + 1][3], aPh[kp][3], aPl[kp][3]);
        }

        // ---- O += P.V  (4 n-tiles of 8 d), 3-term split ----
        #pragma unroll
        for (int nt2 = 0; nt2 < 4; nt2++) {
            const uint8_t* vhr = sVh + (nt2 * 8 + g) * 128;
            const uint8_t* vlr = sVl + (nt2 * 8 + g) * 128;
            const int boff = 4 * tg;
            #pragma unroll
            for (int kp = 0; kp < 4; kp++) {
                uint32_t bv[2], bw[2];
                bv[0] = *reinterpret_cast<const uint32_t*>(vhr + (((2 * kp)     ^ g) << 4) + boff);
                bv[1] = *reinterpret_cast<const uint32_t*>(vhr + (((2 * kp + 1) ^ g) << 4) + boff);
                bw[0] = *reinterpret_cast<const uint32_t*>(vlr + (((2 * kp)     ^ g) << 4) + boff);
                bw[1] = *reinterpret_cast<const uint32_t*>(vlr + (((2 * kp + 1) ^ g) << 4) + boff);
                mma16816(oc[nt2], aPh[kp], bv);   // Ph.Vh
                mma16816(oc[nt2], aPl[kp], bv);   // Pl.Vh
                mma16816(oc[nt2], aPh[kp], bw);   // Ph.Vl
            }
        }
    }

    // ---- epilogue: reduce l across the quad, normalize, store ----
    lsum0 += __shfl_xor_sync(0xFFFFFFFFu, lsum0, 1);
    lsum0 += __shfl_xor_sync(0xFFFFFFFFu, lsum0, 2);
    lsum1 += __shfl_xor_sync(0xFFFFFFFFu, lsum1, 1);
    lsum1 += __shfl_xor_sync(0xFFFFFFFFu, lsum1, 2);
    const float inv0 = 1.0f / lsum0;
    const float inv1 = 1.0f / lsum1;

    const int b = bn >> 3, n = bn & 7;
    const int qrow0 = qbase + warp * 16 + g;
    float* o0 = out + ((size_t)b * SEQ + qrow0) * (HEADS * DIM) + n * DIM;
    float* o1 = o0 + 8 * (HEADS * DIM);
    #pragma unroll
    for (int nt2 = 0; nt2 < 4; nt2++) {
        int d = nt2 * 8 + 2 * tg;
        *reinterpret_cast<float2*>(o0 + d) = make_float2(oc[nt2][0] * inv0, oc[nt2][1] * inv0);
        *reinterpret_cast<float2*>(o1 + d) = make_float2(oc[nt2][2] * inv1, oc[nt2][3] * inv1);
    }
}

extern "C" void kernel_launch(void* const* d_in, const int* in_sizes, int n_in,
                              void* d_out, int out_size)
{
    const float* q  = (const float*)d_in[0];
    const float* k  = (const float*)d_in[1];
    const float* v  = (const float*)d_in[2];
    const float* eh = (const float*)d_in[3];
    const float* ew = (const float*)d_in[4];
    float* out = (float*)d_out;

    dim3 grid(SEQ / QT, BSZ * HEADS);   // 64 x 16 = 1024 CTAs
    abspos_attn_mma<<<grid, THREADS>>>(q, k, v, eh, ew, out);
}

// round 7
// speedup vs baseline: 3.6862x; 1.0843x over previous
#include <cuda_runtime.h>
#include <cuda_bf16.h>
#include <cstdint>

// ---------------- problem constants ----------------
#define BSZ     2
#define HEADS   8
#define DIM     32
#define SEQ     4096
#define QT      128            // queries per CTA (32 per warp, 2 m16 blocks)
#define KT      64             // keys per tile
#define NTILES  (SEQ / KT)     // 64
#define THREADS 128

// pack two f32 -> bf16x2 (x0 in low half)
__device__ __forceinline__ uint32_t cvt2(float lo, float hi) {
    uint32_t r;
    asm("cvt.rn.bf16x2.f32 %0, %1, %2;" : "=r"(r) : "f"(hi), "f"(lo));
    return r;
}
// error-compensated split: (x0,x1) -> hi bf16x2 + lo bf16x2
__device__ __forceinline__ void split2(float x0, float x1, uint32_t& h, uint32_t& l) {
    h = cvt2(x0, x1);
    float h0 = __uint_as_float(h << 16);
    float h1 = __uint_as_float(h & 0xFFFF0000u);
    l = cvt2(x0 - h0, x1 - h1);
}

__device__ __forceinline__ void mma16816(float* c, const uint32_t* a, const uint32_t* b) {
    asm volatile(
        "mma.sync.aligned.m16n8k16.row.col.f32.bf16.bf16.f32 "
        "{%0,%1,%2,%3},{%4,%5,%6,%7},{%8,%9},{%0,%1,%2,%3};"
        : "+f"(c[0]), "+f"(c[1]), "+f"(c[2]), "+f"(c[3])
        : "r"(a[0]), "r"(a[1]), "r"(a[2]), "r"(a[3]), "r"(b[0]), "r"(b[1]));
}

#define LDMX4(r, a) \
    asm volatile("ldmatrix.sync.aligned.m8n8.x4.shared.b16 {%0,%1,%2,%3}, [%4];" \
        : "=r"((r)[0]), "=r"((r)[1]), "=r"((r)[2]), "=r"((r)[3]) : "r"(a))

__device__ __forceinline__ uint32_t smem_u32(const void* p) {
    uint32_t a;
    asm("{ .reg .u64 t; cvta.to.shared.u64 t, %1; cvt.u32.u64 %0, t; }" : "=r"(a) : "l"(p));
    return a;
}

// 16B-chunk XOR swizzle inside a 128B row (staging side)
__device__ __forceinline__ int swz(int row, int chunk) {
    return row * 128 + ((chunk ^ (row & 7)) << 4);
}

__global__ void __launch_bounds__(THREADS, 2)
abspos_attn_mma(const float* __restrict__ q,
                const float* __restrict__ k,
                const float* __restrict__ v,
                const float* __restrict__ eh,
                const float* __restrict__ ew,
                float* __restrict__ out)
{
    // K' rows: 64 keys x 128B = [Kh 32d | Kl 32d] bf16, chunk-swizzled
    // V^T rows: 32 d x 128B = 64 keys bf16, hi and lo buffers
    __shared__ __align__(16) uint8_t sK [64 * 128];
    __shared__ __align__(16) uint8_t sVh[32 * 128];
    __shared__ __align__(16) uint8_t sVl[32 * 128];

    const int tid  = threadIdx.x;
    const int warp = tid >> 5;
    const int lane = tid & 31;
    const int g    = lane >> 2;      // group id 0..7
    const int tg   = lane & 3;       // thread-in-group

    const int bn    = blockIdx.y;            // b*HEADS + n
    const int qbase = blockIdx.x * QT;

    const float4* kb4 = reinterpret_cast<const float4*>(k + (size_t)bn * SEQ * DIM);
    const float*  vb  = v + (size_t)bn * SEQ * DIM;
    const float4* eh4 = reinterpret_cast<const float4*>(eh);
    const float4* ew4 = reinterpret_cast<const float4*>(ew);

    // ---- Q fragments: 2 m16 blocks (rows g,g+8 / g+16,g+24 of warp's 32) ----
    uint32_t aqh[2][2][4], aql[2][2][4];
    {
        const float scale = 0.17677669529663687f;   // 32^-0.5
        #pragma unroll
        for (int mb = 0; mb < 2; mb++) {
            const int qrow0 = qbase + warp * 32 + mb * 16 + g;
            const float* qp0 = q + ((size_t)bn * SEQ + qrow0) * DIM;
            const float* qp1 = qp0 + 8 * DIM;
            #pragma unroll
            for (int ks = 0; ks < 2; ks++) {
                #pragma unroll
                for (int half = 0; half < 2; half++) {
                    int d = 16 * ks + 8 * half + 2 * tg;
                    float2 r0 = *reinterpret_cast<const float2*>(qp0 + d);
                    float2 r1 = *reinterpret_cast<const float2*>(qp1 + d);
                    split2(r0.x * scale, r0.y * scale, aqh[mb][ks][2 * half],     aql[mb][ks][2 * half]);
                    split2(r1.x * scale, r1.y * scale, aqh[mb][ks][2 * half + 1], aql[mb][ks][2 * half + 1]);
                }
            }
        }
    }

    // ---- persistent state ----
    float oc[2][4][4];
    #pragma unroll
    for (int mb = 0; mb < 2; mb++)
        #pragma unroll
        for (int i = 0; i < 4; i++)
            #pragma unroll
            for (int e = 0; e < 4; e++) oc[mb][i][e] = 0.f;
    float ls[2][2] = {{0.f, 0.f}, {0.f, 0.f}};

    // ---- loop-invariant ldmatrix lane addresses (swizzle hoisted) ----
    const int lr = lane & 7, lc = lane >> 3;
    const uint32_t phys = (uint32_t)((lc ^ lr) << 4);
    const uint32_t kmat_hi = smem_u32(sK)  + (uint32_t)(lr * 128) + phys; // d 0-31 (hi)
    const uint32_t vmat_h0 = smem_u32(sVh) + (uint32_t)(lr * 128) + phys; // keys 0-31
    const uint32_t vmat_l0 = smem_u32(sVl) + (uint32_t)(lr * 128) + phys;
    // lo-half / upper-keys addresses are ^64 (chunk+4 under the XOR swizzle)

    // staging thread roles
    const int jk = tid >> 1, hk = tid & 1;     // K': key jk, d-half hk
    const int dv = tid & 31, kg = tid >> 5;    // V : d dv, key-group kg of 16

    #pragma unroll 1
    for (int t = 0; t < NTILES; t++) {
        // ---- stage gmem -> regs ----
        float4 kf[4];
        {
            const float4* kp4 = kb4 + (size_t)t * 512 + jk * 8 + hk * 4;
            #pragma unroll
            for (int i = 0; i < 4; i++) kf[i] = kp4[i];
        }
        float vf[16];
        {
            const float* vp = vb + ((size_t)t * 64 + kg * 16) * DIM + dv;
            #pragma unroll
            for (int i = 0; i < 16; i++) vf[i] = vp[i * DIM];
        }

        __syncthreads();   // previous tile's smem reads complete

        // ---- write K' = K + eh[t] + ew[j], split hi/lo ----
        {
            uint32_t hi[8], lo[8];
            #pragma unroll
            for (int i = 0; i < 4; i++) {
                float4 ev = eh4[t * 8 + hk * 4 + i];
                float4 wv = ew4[jk * 8 + hk * 4 + i];
                float x0 = kf[i].x + ev.x + wv.x;
                float x1 = kf[i].y + ev.y + wv.y;
                float x2 = kf[i].z + ev.z + wv.z;
                float x3 = kf[i].w + ev.w + wv.w;
                split2(x0, x1, hi[2 * i],     lo[2 * i]);
                split2(x2, x3, hi[2 * i + 1], lo[2 * i + 1]);
            }
            *reinterpret_cast<uint4*>(sK + swz(jk, 2 * hk))     = make_uint4(hi[0], hi[1], hi[2], hi[3]);
            *reinterpret_cast<uint4*>(sK + swz(jk, 2 * hk + 1)) = make_uint4(hi[4], hi[5], hi[6], hi[7]);
            *reinterpret_cast<uint4*>(sK + swz(jk, 2 * hk + 4)) = make_uint4(lo[0], lo[1], lo[2], lo[3]);
            *reinterpret_cast<uint4*>(sK + swz(jk, 2 * hk + 5)) = make_uint4(lo[4], lo[5], lo[6], lo[7]);
        }
        // ---- write V^T (d-major), split hi/lo ----
        {
            uint32_t hv[8], lv[8];
            #pragma unroll
            for (int i = 0; i < 8; i++)
                split2(vf[2 * i], vf[2 * i + 1], hv[i], lv[i]);
            *reinterpret_cast<uint4*>(sVh + swz(dv, 2 * kg))     = make_uint4(hv[0], hv[1], hv[2], hv[3]);
            *reinterpret_cast<uint4*>(sVh + swz(dv, 2 * kg + 1)) = make_uint4(hv[4], hv[5], hv[6], hv[7]);
            *reinterpret_cast<uint4*>(sVl + swz(dv, 2 * kg))     = make_uint4(lv[0], lv[1], lv[2], lv[3]);
            *reinterpret_cast<uint4*>(sVl + swz(dv, 2 * kg + 1)) = make_uint4(lv[4], lv[5], lv[6], lv[7]);
        }
        __syncthreads();

        // ---- S = Q'.K'^T : 8 n-tiles x 2 m-blocks, 3-term split ----
        float c[2][8][4];
        #pragma unroll
        for (int nt = 0; nt < 8; nt++) {
            uint32_t bh[4], bl[4];
            LDMX4(bh, kmat_hi + (uint32_t)(nt * 1024));
            LDMX4(bl, (kmat_hi ^ 64u) + (uint32_t)(nt * 1024));
            #pragma unroll
            for (int mb = 0; mb < 2; mb++) {
                #pragma unroll
                for (int e = 0; e < 4; e++) c[mb][nt][e] = 0.f;
                mma16816(c[mb][nt], aqh[mb][0], bh + 0);   // Qh.Kh k0
                mma16816(c[mb][nt], aqh[mb][1], bh + 2);   // Qh.Kh k1
                mma16816(c[mb][nt], aqh[mb][0], bl + 0);   // Qh.Kl k0
                mma16816(c[mb][nt], aqh[mb][1], bl + 2);   // Qh.Kl k1
                mma16816(c[mb][nt], aql[mb][0], bh + 0);   // Ql.Kh k0
                mma16816(c[mb][nt], aql[mb][1], bh + 2);   // Ql.Kh k1
            }
        }

        // ---- softmax (no max subtraction; logits bounded) + repack ----
        uint32_t aPh[2][4][4], aPl[2][4][4];
        #pragma unroll
        for (int mb = 0; mb < 2; mb++) {
            #pragma unroll
            for (int nt = 0; nt < 8; nt++) {
                c[mb][nt][0] = __expf(c[mb][nt][0]);
                c[mb][nt][1] = __expf(c[mb][nt][1]);
                c[mb][nt][2] = __expf(c[mb][nt][2]);
                c[mb][nt][3] = __expf(c[mb][nt][3]);
                ls[mb][0] += c[mb][nt][0] + c[mb][nt][1];
                ls[mb][1] += c[mb][nt][2] + c[mb][nt][3];
            }
            #pragma unroll
            for (int kp = 0; kp < 4; kp++) {
                split2(c[mb][2 * kp][0],     c[mb][2 * kp][1],     aPh[mb][kp][0], aPl[mb][kp][0]);
                split2(c[mb][2 * kp][2],     c[mb][2 * kp][3],     aPh[mb][kp][1], aPl[mb][kp][1]);
                split2(c[mb][2 * kp + 1][0], c[mb][2 * kp + 1][1], aPh[mb][kp][2], aPl[mb][kp][2]);
                split2(c[mb][2 * kp + 1][2], c[mb][2 * kp + 1][3], aPh[mb][kp][3], aPl[mb][kp][3]);
            }
        }

        // ---- O += P.V : 4 n-tiles x 2 m-blocks, 3-term split ----
        #pragma unroll
        for (int nt2 = 0; nt2 < 4; nt2++) {
            uint32_t bv0[4], bv1[4], bw0[4], bw1[4];
            const uint32_t off = (uint32_t)(nt2 * 1024);
            LDMX4(bv0, vmat_h0 + off);            // Vh keys 0-31 (kp 0,1)
            LDMX4(bv1, (vmat_h0 ^ 64u) + off);    // Vh keys 32-63 (kp 2,3)
            LDMX4(bw0, vmat_l0 + off);            // Vl keys 0-31
            LDMX4(bw1, (vmat_l0 ^ 64u) + off);    // Vl keys 32-63
            #pragma unroll
            for (int mb = 0; mb < 2; mb++) {
                mma16816(oc[mb][nt2], aPh[mb][0], bv0 + 0);
                mma16816(oc[mb][nt2], aPh[mb][1], bv0 + 2);
                mma16816(oc[mb][nt2], aPh[mb][2], bv1 + 0);
                mma16816(oc[mb][nt2], aPh[mb][3], bv1 + 2);
                mma16816(oc[mb][nt2], aPl[mb][0], bv0 + 0);
                mma16816(oc[mb][nt2], aPl[mb][1], bv0 + 2);
                mma16816(oc[mb][nt2], aPl[mb][2], bv1 + 0);
                mma16816(oc[mb][nt2], aPl[mb][3], bv1 + 2);
                mma16816(oc[mb][nt2], aPh[mb][0], bw0 + 0);
                mma16816(oc[mb][nt2], aPh[mb][1], bw0 + 2);
                mma16816(oc[mb][nt2], aPh[mb][2], bw1 + 0);
                mma16816(oc[mb][nt2], aPh[mb][3], bw1 + 2);
            }
        }
    }

    // ---- epilogue: reduce l across the quad, normalize, store ----
    const int b = bn >> 3, n = bn & 7;
    #pragma unroll
    for (int mb = 0; mb < 2; mb++) {
        float l0 = ls[mb][0], l1 = ls[mb][1];
        l0 += __shfl_xor_sync(0xFFFFFFFFu, l0, 1);
        l0 += __shfl_xor_sync(0xFFFFFFFFu, l0, 2);
        l1 += __shfl_xor_sync(0xFFFFFFFFu, l1, 1);
        l1 += __shfl_xor_sync(0xFFFFFFFFu, l1, 2);
        const float inv0 = 1.0f / l0;
        const float inv1 = 1.0f / l1;
        const int qrow0 = qbase + warp * 32 + mb * 16 + g;
        float* o0 = out + ((size_t)b * SEQ + qrow0) * (HEADS * DIM) + n * DIM;
        float* o1 = o0 + 8 * (HEADS * DIM);
        #pragma unroll
        for (int nt2 = 0; nt2 < 4; nt2++) {
            int d = nt2 * 8 + 2 * tg;
            *reinterpret_cast<float2*>(o0 + d) =
                make_float2(oc[mb][nt2][0] * inv0, oc[mb][nt2][1] * inv0);
            *reinterpret_cast<float2*>(o1 + d) =
                make_float2(oc[mb][nt2][2] * inv1, oc[mb][nt2][3] * inv1);
        }
    }
}

extern "C" void kernel_launch(void* const* d_in, const int* in_sizes, int n_in,
                              void* d_out, int out_size)
{
    const float* q  = (const float*)d_in[0];
    const float* k  = (const float*)d_in[1];
    const float* v  = (const float*)d_in[2];
    const float* eh = (const float*)d_in[3];
    const float* ew = (const float*)d_in[4];
    float* out = (float*)d_out;

    dim3 grid(SEQ / QT, BSZ * HEADS);   // 32 x 16 = 512 CTAs
    abspos_attn_mma<<<grid, THREADS>>>(q, k, v, eh, ew, out);
}

// round 9
// speedup vs baseline: 4.4066x; 1.1954x over previous
#include <cuda_runtime.h>
#include <cuda_bf16.h>
#include <cstdint>

// ---------------- problem constants ----------------
#define BSZ     2
#define HEADS   8
#define DIM     32
#define SEQ     4096
#define QT      128            // queries per CTA (32 per warp, 2 m16 blocks)
#define KT      64             // keys per tile
#define NTILES  (SEQ / KT)     // 64
#define THREADS 128

// pack two f32 -> bf16x2 (x0 in low half)
__device__ __forceinline__ uint32_t cvt2(float lo, float hi) {
    uint32_t r;
    asm("cvt.rn.bf16x2.f32 %0, %1, %2;" : "=r"(r) : "f"(hi), "f"(lo));
    return r;
}
// error-compensated split: (x0,x1) -> hi bf16x2 + lo bf16x2
__device__ __forceinline__ void split2(float x0, float x1, uint32_t& h, uint32_t& l) {
    h = cvt2(x0, x1);
    float h0 = __uint_as_float(h << 16);
    float h1 = __uint_as_float(h & 0xFFFF0000u);
    l = cvt2(x0 - h0, x1 - h1);
}

__device__ __forceinline__ float ex2f(float x) {
    float y; asm("ex2.approx.ftz.f32 %0, %1;" : "=f"(y) : "f"(x)); return y;
}

__device__ __forceinline__ void mma16816(float* c, const uint32_t* a, const uint32_t* b) {
    asm volatile(
        "mma.sync.aligned.m16n8k16.row.col.f32.bf16.bf16.f32 "
        "{%0,%1,%2,%3},{%4,%5,%6,%7},{%8,%9},{%0,%1,%2,%3};"
        : "+f"(c[0]), "+f"(c[1]), "+f"(c[2]), "+f"(c[3])
        : "r"(a[0]), "r"(a[1]), "r"(a[2]), "r"(a[3]), "r"(b[0]), "r"(b[1]));
}

#define LDMX4(r, a) \
    asm volatile("ldmatrix.sync.aligned.m8n8.x4.shared.b16 {%0,%1,%2,%3}, [%4];" \
        : "=r"((r)[0]), "=r"((r)[1]), "=r"((r)[2]), "=r"((r)[3]) : "r"(a))

__device__ __forceinline__ uint32_t smem_u32(const void* p) {
    uint32_t a;
    asm("{ .reg .u64 t; cvta.to.shared.u64 t, %1; cvt.u32.u64 %0, t; }" : "=r"(a) : "l"(p));
    return a;
}

// 16B-chunk XOR swizzle inside a 128B row (staging side)
__device__ __forceinline__ int swz(int row, int chunk) {
    return row * 128 + ((chunk ^ (row & 7)) << 4);
}

#define KBUF (64 * 128)
#define VBUF (32 * 128)

__global__ void __launch_bounds__(THREADS, 2)
abspos_attn_mma(const float* __restrict__ q,
                const float* __restrict__ k,
                const float* __restrict__ v,
                const float* __restrict__ eh,
                const float* __restrict__ ew,
                float* __restrict__ out)
{
    // double-buffered tiles
    // K' rows: 64 keys x 128B = [Kh 32d | Kl 32d] bf16, chunk-swizzled
    // V^T rows: 32 d x 128B = 64 keys bf16, hi and lo buffers
    __shared__ __align__(16) uint8_t sK [2][KBUF];
    __shared__ __align__(16) uint8_t sVh[2][VBUF];
    __shared__ __align__(16) uint8_t sVl[2][VBUF];

    const int tid  = threadIdx.x;
    const int warp = tid >> 5;
    const int lane = tid & 31;
    const int g    = lane >> 2;      // group id 0..7
    const int tg   = lane & 3;       // thread-in-group

    const int bn    = blockIdx.y;            // b*HEADS + n
    const int qbase = blockIdx.x * QT;

    const float4* kb4 = reinterpret_cast<const float4*>(k + (size_t)bn * SEQ * DIM);
    const float*  vb  = v + (size_t)bn * SEQ * DIM;
    const float4* eh4 = reinterpret_cast<const float4*>(eh);
    const float4* ew4 = reinterpret_cast<const float4*>(ew);

    // ---- Q fragments: 2 m16 blocks; scale folds 1/sqrt(D) AND log2(e) ----
    uint32_t aqh[2][2][4], aql[2][2][4];
    {
        const float scale = 0.17677669529663687f * 1.4426950408889634f;
        #pragma unroll
        for (int mb = 0; mb < 2; mb++) {
            const int qrow0 = qbase + warp * 32 + mb * 16 + g;
            const float* qp0 = q + ((size_t)bn * SEQ + qrow0) * DIM;
            const float* qp1 = qp0 + 8 * DIM;
            #pragma unroll
            for (int ks = 0; ks < 2; ks++) {
                #pragma unroll
                for (int half = 0; half < 2; half++) {
                    int d = 16 * ks + 8 * half + 2 * tg;
                    float2 r0 = *reinterpret_cast<const float2*>(qp0 + d);
                    float2 r1 = *reinterpret_cast<const float2*>(qp1 + d);
                    split2(r0.x * scale, r0.y * scale, aqh[mb][ks][2 * half],     aql[mb][ks][2 * half]);
                    split2(r1.x * scale, r1.y * scale, aqh[mb][ks][2 * half + 1], aql[mb][ks][2 * half + 1]);
                }
            }
        }
    }

    // ---- persistent state ----
    float oc[2][4][4];
    #pragma unroll
    for (int mb = 0; mb < 2; mb++)
        #pragma unroll
        for (int i = 0; i < 4; i++)
            #pragma unroll
            for (int e = 0; e < 4; e++) oc[mb][i][e] = 0.f;
    float ls[2][2] = {{0.f, 0.f}, {0.f, 0.f}};

    // ---- loop-invariant ldmatrix lane addresses (swizzle hoisted) ----
    const int lr = lane & 7, lc = lane >> 3;
    const uint32_t phys = (uint32_t)((lc ^ lr) << 4);
    const uint32_t kmat0 = smem_u32(sK)  + (uint32_t)(lr * 128) + phys; // buf0, d 0-31 hi
    const uint32_t vhm0  = smem_u32(sVh) + (uint32_t)(lr * 128) + phys;
    const uint32_t vlm0  = smem_u32(sVl) + (uint32_t)(lr * 128) + phys;
    // lo-half / upper-keys addresses are ^64 (chunk+4 under the XOR swizzle)

    // staging thread roles
    const int jk = tid >> 1, hk = tid & 1;     // K': key jk, d-half hk
    const int dv = tid & 31, kg = tid >> 5;    // V : d dv, key-group kg of 16

    // ================= staging macro: tile tt -> buffer b =================
#define STAGE(tt, b) do {                                                         \
        float4 kf[4];                                                             \
        const float4* kp4 = kb4 + (size_t)(tt) * 512 + jk * 8 + hk * 4;           \
        _Pragma("unroll")                                                         \
        for (int i = 0; i < 4; i++) kf[i] = kp4[i];                               \
        float vf[16];                                                             \
        const float* vp = vb + ((size_t)(tt) * 64 + kg * 16) * DIM + dv;          \
        _Pragma("unroll")                                                         \
        for (int i = 0; i < 16; i++) vf[i] = vp[i * DIM];                         \
        uint32_t hi[8], lo[8];                                                    \
        _Pragma("unroll")                                                         \
        for (int i = 0; i < 4; i++) {                                             \
            float4 ev = eh4[(tt) * 8 + hk * 4 + i];                               \
            float4 wv = ew4[jk * 8 + hk * 4 + i];                                 \
            float x0 = kf[i].x + ev.x + wv.x;                                     \
            float x1 = kf[i].y + ev.y + wv.y;                                     \
            float x2 = kf[i].z + ev.z + wv.z;                                     \
            float x3 = kf[i].w + ev.w + wv.w;                                     \
            split2(x0, x1, hi[2 * i],     lo[2 * i]);                             \
            split2(x2, x3, hi[2 * i + 1], lo[2 * i + 1]);                         \
        }                                                                         \
        uint8_t* dK = sK[b];                                                      \
        *reinterpret_cast<uint4*>(dK + swz(jk, 2 * hk))     = make_uint4(hi[0], hi[1], hi[2], hi[3]); \
        *reinterpret_cast<uint4*>(dK + swz(jk, 2 * hk + 1)) = make_uint4(hi[4], hi[5], hi[6], hi[7]); \
        *reinterpret_cast<uint4*>(dK + swz(jk, 2 * hk + 4)) = make_uint4(lo[0], lo[1], lo[2], lo[3]); \
        *reinterpret_cast<uint4*>(dK + swz(jk, 2 * hk + 5)) = make_uint4(lo[4], lo[5], lo[6], lo[7]); \
        uint32_t hv[8], lv[8];                                                    \
        _Pragma("unroll")                                                         \
        for (int i = 0; i < 8; i++) split2(vf[2 * i], vf[2 * i + 1], hv[i], lv[i]); \
        uint8_t* dVh = sVh[b];                                                    \
        uint8_t* dVl = sVl[b];                                                    \
        *reinterpret_cast<uint4*>(dVh + swz(dv, 2 * kg))     = make_uint4(hv[0], hv[1], hv[2], hv[3]); \
        *reinterpret_cast<uint4*>(dVh + swz(dv, 2 * kg + 1)) = make_uint4(hv[4], hv[5], hv[6], hv[7]); \
        *reinterpret_cast<uint4*>(dVl + swz(dv, 2 * kg))     = make_uint4(lv[0], lv[1], lv[2], lv[3]); \
        *reinterpret_cast<uint4*>(dVl + swz(dv, 2 * kg + 1)) = make_uint4(lv[4], lv[5], lv[6], lv[7]); \
    } while (0)
    // ======================================================================

    STAGE(0, 0);
    __syncthreads();

    #pragma unroll 1
    for (int t = 0; t < NTILES; t++) {
        const int cur = t & 1;
        if (t + 1 < NTILES) {
            STAGE(t + 1, cur ^ 1);   // other buffer: safe, one barrier behind
        }

        const uint32_t kmat = kmat0 + (uint32_t)(cur * KBUF);
        const uint32_t vhm  = vhm0  + (uint32_t)(cur * VBUF);
        const uint32_t vlm  = vlm0  + (uint32_t)(cur * VBUF);

        // ---- S = Q'.K'^T : 8 n-tiles x 2 m-blocks, 3-term split ----
        float c[2][8][4];
        #pragma unroll
        for (int nt = 0; nt < 8; nt++) {
            uint32_t bh[4], bl[4];
            LDMX4(bh, kmat + (uint32_t)(nt * 1024));
            LDMX4(bl, (kmat ^ 64u) + (uint32_t)(nt * 1024));
            #pragma unroll
            for (int mb = 0; mb < 2; mb++) {
                #pragma unroll
                for (int e = 0; e < 4; e++) c[mb][nt][e] = 0.f;
                mma16816(c[mb][nt], aqh[mb][0], bh + 0);   // Qh.Kh k0
                mma16816(c[mb][nt], aqh[mb][1], bh + 2);   // Qh.Kh k1
                mma16816(c[mb][nt], aqh[mb][0], bl + 0);   // Qh.Kl k0
                mma16816(c[mb][nt], aqh[mb][1], bl + 2);   // Qh.Kl k1
                mma16816(c[mb][nt], aql[mb][0], bh + 0);   // Ql.Kh k0
                mma16816(c[mb][nt], aql[mb][1], bh + 2);   // Ql.Kh k1
            }
        }

        // ---- softmax: p = 2^S (log2e folded into Q scale) + repack ----
        uint32_t aPh[2][4][4], aPl[2][4][4];
        #pragma unroll
        for (int mb = 0; mb < 2; mb++) {
            #pragma unroll
            for (int nt = 0; nt < 8; nt++) {
                c[mb][nt][0] = ex2f(c[mb][nt][0]);
                c[mb][nt][1] = ex2f(c[mb][nt][1]);
                c[mb][nt][2] = ex2f(c[mb][nt][2]);
                c[mb][nt][3] = ex2f(c[mb][nt][3]);
                ls[mb][0] += c[mb][nt][0] + c[mb][nt][1];
                ls[mb][1] += c[mb][nt][2] + c[mb][nt][3];
            }
            #pragma unroll
            for (int kp = 0; kp < 4; kp++) {
                split2(c[mb][2 * kp][0],     c[mb][2 * kp][1],     aPh[mb][kp][0], aPl[mb][kp][0]);
                split2(c[mb][2 * kp][2],     c[mb][2 * kp][3],     aPh[mb][kp][1], aPl[mb][kp][1]);
                split2(c[mb][2 * kp + 1][0], c[mb][2 * kp + 1][1], aPh[mb][kp][2], aPl[mb][kp][2]);
                split2(c[mb][2 * kp + 1][2], c[mb][2 * kp + 1][3], aPh[mb][kp][3], aPl[mb][kp][3]);
            }
        }

        // ---- O += P.V : 4 n-tiles x 2 m-blocks, 3-term split ----
        #pragma unroll
        for (int nt2 = 0; nt2 < 4; nt2++) {
            uint32_t bv0[4], bv1[4], bw0[4], bw1[4];
            const uint32_t off = (uint32_t)(nt2 * 1024);
            LDMX4(bv0, vhm + off);            // Vh keys 0-31 (kp 0,1)
            LDMX4(bv1, (vhm ^ 64u) + off);    // Vh keys 32-63 (kp 2,3)
            LDMX4(bw0, vlm + off);            // Vl keys 0-31
            LDMX4(bw1, (vlm ^ 64u) + off);    // Vl keys 32-63
            #pragma unroll
            for (int mb = 0; mb < 2; mb++) {
                mma16816(oc[mb][nt2], aPh[mb][0], bv0 + 0);
                mma16816(oc[mb][nt2], aPh[mb][1], bv0 + 2);
                mma16816(oc[mb][nt2], aPh[mb][2], bv1 + 0);
                mma16816(oc[mb][nt2], aPh[mb][3], bv1 + 2);
                mma16816(oc[mb][nt2], aPl[mb][0], bv0 + 0);
                mma16816(oc[mb][nt2], aPl[mb][1], bv0 + 2);
                mma16816(oc[mb][nt2], aPl[mb][2], bv1 + 0);
                mma16816(oc[mb][nt2], aPl[mb][3], bv1 + 2);
                mma16816(oc[mb][nt2], aPh[mb][0], bw0 + 0);
                mma16816(oc[mb][nt2], aPh[mb][1], bw0 + 2);
                mma16816(oc[mb][nt2], aPh[mb][2], bw1 + 0);
                mma16816(oc[mb][nt2], aPh[mb][3], bw1 + 2);
            }
        }

        __syncthreads();   // single barrier per tile
    }

    // ---- epilogue: reduce l across the quad, normalize, store ----
    const int b = bn >> 3, n = bn & 7;
    #pragma unroll
    for (int mb = 0; mb < 2; mb++) {
        float l0 = ls[mb][0], l1 = ls[mb][1];
        l0 += __shfl_xor_sync(0xFFFFFFFFu, l0, 1);
        l0 += __shfl_xor_sync(0xFFFFFFFFu, l0, 2);
        l1 += __shfl_xor_sync(0xFFFFFFFFu, l1, 1);
        l1 += __shfl_xor_sync(0xFFFFFFFFu, l1, 2);
        const float inv0 = 1.0f / l0;
        const float inv1 = 1.0f / l1;
        const int qrow0 = qbase + warp * 32 + mb * 16 + g;
        float* o0 = out + ((size_t)b * SEQ + qrow0) * (HEADS * DIM) + n * DIM;
        float* o1 = o0 + 8 * (HEADS * DIM);
        #pragma unroll
        for (int nt2 = 0; nt2 < 4; nt2++) {
            int d = nt2 * 8 + 2 * tg;
            *reinterpret_cast<float2*>(o0 + d) =
                make_float2(oc[mb][nt2][0] * inv0, oc[mb][nt2][1] * inv0);
            *reinterpret_cast<float2*>(o1 + d) =
                make_float2(oc[mb][nt2][2] * inv1, oc[mb][nt2][3] * inv1);
        }
    }
}

extern "C" void kernel_launch(void* const* d_in, const int* in_sizes, int n_in,
                              void* d_out, int out_size)
{
    const float* q  = (const float*)d_in[0];
    const float* k  = (const float*)d_in[1];
    const float* v  = (const float*)d_in[2];
    const float* eh = (const float*)d_in[3];
    const float* ew = (const float*)d_in[4];
    float* out = (float*)d_out;

    dim3 grid(SEQ / QT, BSZ * HEADS);   // 32 x 16 = 512 CTAs
    abspos_attn_mma<<<grid, THREADS>>>(q, k, v, eh, ew, out);
}

// round 10
// speedup vs baseline: 4.4895x; 1.0188x over previous
#include <cuda_runtime.h>
#include <cuda_bf16.h>
#include <cstdint>

// ---------------- problem constants ----------------
#define BSZ     2
#define HEADS   8
#define DIM     32
#define SEQ     4096
#define QT      128            // queries per CTA (32 per warp, 2 m16 blocks)
#define KT      64             // keys per tile
#define NTILES  (SEQ / KT)     // 64
#define THREADS 128

// pack two f32 -> bf16x2 (x0 in low half)
__device__ __forceinline__ uint32_t cvt2(float lo, float hi) {
    uint32_t r;
    asm("cvt.rn.bf16x2.f32 %0, %1, %2;" : "=r"(r) : "f"(hi), "f"(lo));
    return r;
}
// error-compensated split: (x0,x1) -> hi bf16x2 + lo bf16x2
__device__ __forceinline__ void split2(float x0, float x1, uint32_t& h, uint32_t& l) {
    h = cvt2(x0, x1);
    float h0 = __uint_as_float(h << 16);
    float h1 = __uint_as_float(h & 0xFFFF0000u);
    l = cvt2(x0 - h0, x1 - h1);
}

__device__ __forceinline__ float ex2f(float x) {
    float y; asm("ex2.approx.ftz.f32 %0, %1;" : "=f"(y) : "f"(x)); return y;
}

__device__ __forceinline__ void mma16816(float* c, const uint32_t* a, const uint32_t* b) {
    asm volatile(
        "mma.sync.aligned.m16n8k16.row.col.f32.bf16.bf16.f32 "
        "{%0,%1,%2,%3},{%4,%5,%6,%7},{%8,%9},{%0,%1,%2,%3};"
        : "+f"(c[0]), "+f"(c[1]), "+f"(c[2]), "+f"(c[3])
        : "r"(a[0]), "r"(a[1]), "r"(a[2]), "r"(a[3]), "r"(b[0]), "r"(b[1]));
}

#define LDMX4(r, a) \
    asm volatile("ldmatrix.sync.aligned.m8n8.x4.shared.b16 {%0,%1,%2,%3}, [%4];" \
        : "=r"((r)[0]), "=r"((r)[1]), "=r"((r)[2]), "=r"((r)[3]) : "r"(a))

__device__ __forceinline__ uint32_t smem_u32(const void* p) {
    uint32_t a;
    asm("{ .reg .u64 t; cvta.to.shared.u64 t, %1; cvt.u32.u64 %0, t; }" : "=r"(a) : "l"(p));
    return a;
}

// 16B-chunk XOR swizzle inside a 128B row (staging side)
__device__ __forceinline__ int swz(int row, int chunk) {
    return row * 128 + ((chunk ^ (row & 7)) << 4);
}

#define KBUF (64 * 128)
#define VBUF (32 * 128)

__global__ void __launch_bounds__(THREADS, 2)
abspos_attn_mma(const float* __restrict__ q,
                const float* __restrict__ k,
                const float* __restrict__ v,
                const float* __restrict__ eh,
                const float* __restrict__ ew,
                float* __restrict__ out)
{
    // double-buffered tiles
    // K' rows: 64 keys x 128B = [Kh 32d | Kl 32d] bf16, chunk-swizzled
    // V^T rows: 32 d x 128B = 64 keys bf16, hi and lo buffers
    __shared__ __align__(16) uint8_t sK [2][KBUF];
    __shared__ __align__(16) uint8_t sVh[2][VBUF];
    __shared__ __align__(16) uint8_t sVl[2][VBUF];

    const int tid  = threadIdx.x;
    const int warp = tid >> 5;
    const int lane = tid & 31;
    const int g    = lane >> 2;      // group id 0..7
    const int tg   = lane & 3;       // thread-in-group

    const int bn    = blockIdx.y;            // b*HEADS + n
    const int qbase = blockIdx.x * QT;

    const float4* kb4 = reinterpret_cast<const float4*>(k + (size_t)bn * SEQ * DIM);
    const float*  vb  = v + (size_t)bn * SEQ * DIM;
    const float4* eh4 = reinterpret_cast<const float4*>(eh);
    const float4* ew4 = reinterpret_cast<const float4*>(ew);

    // staging thread roles
    const int jk = tid >> 1, hk = tid & 1;     // K': key jk, d-half hk
    const int dv = tid & 31, kg = tid >> 5;    // V : d dv, key-group kg of 16

    // loop-invariant ew bias for this thread's staged K chunk
    float4 ewv[4];
    #pragma unroll
    for (int i = 0; i < 4; i++) ewv[i] = ew4[jk * 8 + hk * 4 + i];

    // ---- Q fragments: 2 m16 blocks; scale folds 1/sqrt(D) AND log2(e) ----
    uint32_t aqh[2][2][4], aql[2][2][4];
    {
        const float scale = 0.17677669529663687f * 1.4426950408889634f;
        #pragma unroll
        for (int mb = 0; mb < 2; mb++) {
            const int qrow0 = qbase + warp * 32 + mb * 16 + g;
            const float* qp0 = q + ((size_t)bn * SEQ + qrow0) * DIM;
            const float* qp1 = qp0 + 8 * DIM;
            #pragma unroll
            for (int ks = 0; ks < 2; ks++) {
                #pragma unroll
                for (int half = 0; half < 2; half++) {
                    int d = 16 * ks + 8 * half + 2 * tg;
                    float2 r0 = *reinterpret_cast<const float2*>(qp0 + d);
                    float2 r1 = *reinterpret_cast<const float2*>(qp1 + d);
                    split2(r0.x * scale, r0.y * scale, aqh[mb][ks][2 * half],     aql[mb][ks][2 * half]);
                    split2(r1.x * scale, r1.y * scale, aqh[mb][ks][2 * half + 1], aql[mb][ks][2 * half + 1]);
                }
            }
        }
    }

    // ---- persistent state ----
    float oc[2][4][4];
    #pragma unroll
    for (int mb = 0; mb < 2; mb++)
        #pragma unroll
        for (int i = 0; i < 4; i++)
            #pragma unroll
            for (int e = 0; e < 4; e++) oc[mb][i][e] = 0.f;
    float ls[2][2] = {{0.f, 0.f}, {0.f, 0.f}};

    // ---- loop-invariant ldmatrix lane addresses (swizzle hoisted) ----
    const int lr = lane & 7, lc = lane >> 3;
    const uint32_t phys = (uint32_t)((lc ^ lr) << 4);
    const uint32_t kmat0 = smem_u32(sK)  + (uint32_t)(lr * 128) + phys; // buf0, d 0-31 hi
    const uint32_t vhm0  = smem_u32(sVh) + (uint32_t)(lr * 128) + phys;
    const uint32_t vlm0  = smem_u32(sVl) + (uint32_t)(lr * 128) + phys;
    // lo-half / upper-keys addresses are ^64 (chunk+4 under the XOR swizzle)

    // ================= staging macro: tile tt -> buffer b =================
#define STAGE(tt, b) do {                                                         \
        float4 kf[4];                                                             \
        const float4* kp4 = kb4 + (size_t)(tt) * 512 + jk * 8 + hk * 4;           \
        _Pragma("unroll")                                                         \
        for (int i = 0; i < 4; i++) kf[i] = kp4[i];                               \
        float vf[16];                                                             \
        const float* vp = vb + ((size_t)(tt) * 64 + kg * 16) * DIM + dv;          \
        _Pragma("unroll")                                                         \
        for (int i = 0; i < 16; i++) vf[i] = vp[i * DIM];                         \
        uint32_t hi[8], lo[8];                                                    \
        _Pragma("unroll")                                                         \
        for (int i = 0; i < 4; i++) {                                             \
            float4 ev = eh4[(tt) * 8 + hk * 4 + i];                               \
            float x0 = kf[i].x + ev.x + ewv[i].x;                                 \
            float x1 = kf[i].y + ev.y + ewv[i].y;                                 \
            float x2 = kf[i].z + ev.z + ewv[i].z;                                 \
            float x3 = kf[i].w + ev.w + ewv[i].w;                                 \
            split2(x0, x1, hi[2 * i],     lo[2 * i]);                             \
            split2(x2, x3, hi[2 * i + 1], lo[2 * i + 1]);                         \
        }                                                                         \
        uint8_t* dK = sK[b];                                                      \
        *reinterpret_cast<uint4*>(dK + swz(jk, 2 * hk))     = make_uint4(hi[0], hi[1], hi[2], hi[3]); \
        *reinterpret_cast<uint4*>(dK + swz(jk, 2 * hk + 1)) = make_uint4(hi[4], hi[5], hi[6], hi[7]); \
        *reinterpret_cast<uint4*>(dK + swz(jk, 2 * hk + 4)) = make_uint4(lo[0], lo[1], lo[2], lo[3]); \
        *reinterpret_cast<uint4*>(dK + swz(jk, 2 * hk + 5)) = make_uint4(lo[4], lo[5], lo[6], lo[7]); \
        uint32_t hv[8], lv[8];                                                    \
        _Pragma("unroll")                                                         \
        for (int i = 0; i < 8; i++) split2(vf[2 * i], vf[2 * i + 1], hv[i], lv[i]); \
        uint8_t* dVh = sVh[b];                                                    \
        uint8_t* dVl = sVl[b];                                                    \
        *reinterpret_cast<uint4*>(dVh + swz(dv, 2 * kg))     = make_uint4(hv[0], hv[1], hv[2], hv[3]); \
        *reinterpret_cast<uint4*>(dVh + swz(dv, 2 * kg + 1)) = make_uint4(hv[4], hv[5], hv[6], hv[7]); \
        *reinterpret_cast<uint4*>(dVl + swz(dv, 2 * kg))     = make_uint4(lv[0], lv[1], lv[2], lv[3]); \
        *reinterpret_cast<uint4*>(dVl + swz(dv, 2 * kg + 1)) = make_uint4(lv[4], lv[5], lv[6], lv[7]); \
    } while (0)
    // ======================================================================

    STAGE(0, 0);
    __syncthreads();

    #pragma unroll 1
    for (int t = 0; t < NTILES; t++) {
        const int cur = t & 1;
        if (t + 1 < NTILES) {
            STAGE(t + 1, cur ^ 1);   // other buffer: safe, one barrier behind
        }

        const uint32_t kmat = kmat0 + (uint32_t)(cur * KBUF);
        const uint32_t vhm  = vhm0  + (uint32_t)(cur * VBUF);
        const uint32_t vlm  = vlm0  + (uint32_t)(cur * VBUF);

        // ---- per-m16-block pipeline: QK -> softmax -> PV, two independent
        //      streams in one basic block so ptxas can cross-schedule ----
        #pragma unroll
        for (int mb = 0; mb < 2; mb++) {
            // S = Q'.K'^T : 8 n-tiles, 3-term split
            float c[8][4];
            #pragma unroll
            for (int nt = 0; nt < 8; nt++) {
                uint32_t bh[4], bl[4];
                LDMX4(bh, kmat + (uint32_t)(nt * 1024));
                LDMX4(bl, (kmat ^ 64u) + (uint32_t)(nt * 1024));
                #pragma unroll
                for (int e = 0; e < 4; e++) c[nt][e] = 0.f;
                mma16816(c[nt], aqh[mb][0], bh + 0);   // Qh.Kh k0
                mma16816(c[nt], aqh[mb][1], bh + 2);   // Qh.Kh k1
                mma16816(c[nt], aqh[mb][0], bl + 0);   // Qh.Kl k0
                mma16816(c[nt], aqh[mb][1], bl + 2);   // Qh.Kl k1
                mma16816(c[nt], aql[mb][0], bh + 0);   // Ql.Kh k0
                mma16816(c[nt], aql[mb][1], bh + 2);   // Ql.Kh k1
            }

            // softmax: p = 2^S (log2e folded into Q scale) + repack to A-frags
            uint32_t aPh[4][4], aPl[4][4];
            float l0 = 0.f, l1 = 0.f;
            #pragma unroll
            for (int nt = 0; nt < 8; nt++) {
                c[nt][0] = ex2f(c[nt][0]);
                c[nt][1] = ex2f(c[nt][1]);
                c[nt][2] = ex2f(c[nt][2]);
                c[nt][3] = ex2f(c[nt][3]);
                l0 += c[nt][0] + c[nt][1];
                l1 += c[nt][2] + c[nt][3];
            }
            ls[mb][0] += l0;
            ls[mb][1] += l1;
            #pragma unroll
            for (int kp = 0; kp < 4; kp++) {
                split2(c[2 * kp][0],     c[2 * kp][1],     aPh[kp][0], aPl[kp][0]);
                split2(c[2 * kp][2],     c[2 * kp][3],     aPh[kp][1], aPl[kp][1]);
                split2(c[2 * kp + 1][0], c[2 * kp + 1][1], aPh[kp][2], aPl[kp][2]);
                split2(c[2 * kp + 1][2], c[2 * kp + 1][3], aPh[kp][3], aPl[kp][3]);
            }

            // O += P.V : 4 n-tiles, 3-term split
            #pragma unroll
            for (int nt2 = 0; nt2 < 4; nt2++) {
                uint32_t bv0[4], bv1[4], bw0[4], bw1[4];
                const uint32_t off = (uint32_t)(nt2 * 1024);
                LDMX4(bv0, vhm + off);            // Vh keys 0-31 (kp 0,1)
                LDMX4(bv1, (vhm ^ 64u) + off);    // Vh keys 32-63 (kp 2,3)
                LDMX4(bw0, vlm + off);            // Vl keys 0-31
                LDMX4(bw1, (vlm ^ 64u) + off);    // Vl keys 32-63
                mma16816(oc[mb][nt2], aPh[0], bv0 + 0);
                mma16816(oc[mb][nt2], aPh[1], bv0 + 2);
                mma16816(oc[mb][nt2], aPh[2], bv1 + 0);
                mma16816(oc[mb][nt2], aPh[3], bv1 + 2);
                mma16816(oc[mb][nt2], aPl[0], bv0 + 0);
                mma16816(oc[mb][nt2], aPl[1], bv0 + 2);
                mma16816(oc[mb][nt2], aPl[2], bv1 + 0);
                mma16816(oc[mb][nt2], aPl[3], bv1 + 2);
                mma16816(oc[mb][nt2], aPh[0], bw0 + 0);
                mma16816(oc[mb][nt2], aPh[1], bw0 + 2);
                mma16816(oc[mb][nt2], aPh[2], bw1 + 0);
                mma16816(oc[mb][nt2], aPh[3], bw1 + 2);
            }
        }

        __syncthreads();   // single barrier per tile
    }

    // ---- epilogue: reduce l across the quad, normalize, store ----
    const int b = bn >> 3, n = bn & 7;
    #pragma unroll
    for (int mb = 0; mb < 2; mb++) {
        float l0 = ls[mb][0], l1 = ls[mb][1];
        l0 += __shfl_xor_sync(0xFFFFFFFFu, l0, 1);
        l0 += __shfl_xor_sync(0xFFFFFFFFu, l0, 2);
        l1 += __shfl_xor_sync(0xFFFFFFFFu, l1, 1);
        l1 += __shfl_xor_sync(0xFFFFFFFFu, l1, 2);
        const float inv0 = 1.0f / l0;
        const float inv1 = 1.0f / l1;
        const int qrow0 = qbase + warp * 32 + mb * 16 + g;
        float* o0 = out + ((size_t)b * SEQ + qrow0) * (HEADS * DIM) + n * DIM;
        float* o1 = o0 + 8 * (HEADS * DIM);
        #pragma unroll
        for (int nt2 = 0; nt2 < 4; nt2++) {
            int d = nt2 * 8 + 2 * tg;
            *reinterpret_cast<float2*>(o0 + d) =
                make_float2(oc[mb][nt2][0] * inv0, oc[mb][nt2][1] * inv0);
            *reinterpret_cast<float2*>(o1 + d) =
                make_float2(oc[mb][nt2][2] * inv1, oc[mb][nt2][3] * inv1);
        }
    }
}

extern "C" void kernel_launch(void* const* d_in, const int* in_sizes, int n_in,
                              void* d_out, int out_size)
{
    const float* q  = (const float*)d_in[0];
    const float* k  = (const float*)d_in[1];
    const float* v  = (const float*)d_in[2];
    const float* eh = (const float*)d_in[3];
    const float* ew = (const float*)d_in[4];
    float* out = (float*)d_out;

    dim3 grid(SEQ / QT, BSZ * HEADS);   // 32 x 16 = 512 CTAs
    abspos_attn_mma<<<grid, THREADS>>>(q, k, v, eh, ew, out);
}